// round 16
// baseline (speedup 1.0000x reference)
#include <cuda_runtime.h>
#include <cuda_bf16.h>
#include <math.h>
#include <limits.h>
#include <stdint.h>

// ---------------- problem constants ----------------
#define NATOM  32769
#define NBOND  131073
#define NREAL  32768
#define HDIM   300
#define H3     900
#define H2     600
#define MOLS   512
#define APM    64
#define MAXNB  6
#define AFD    133
#define BFD    147

// padded K dims (multiples of 32) and padded weight-row dims
#define KP_ATOM 192
#define KP_BOND 192
#define KP_H    320
#define KP_H3   960
#define KP_H2   640
#define NP_H    320
#define NP_H3   960

// ---------------- device scratch ----------------
__device__ float g_input_atom[(size_t)NATOM * HDIM];
__device__ float g_input_bond[(size_t)NBOND * HDIM];
__device__ float g_msg_atom  [(size_t)NATOM * HDIM];
__device__ float g_msg_bond  [(size_t)NBOND * HDIM];
__device__ float g_node      [(size_t)NATOM * HDIM];
__device__ float g_gi_f      [(size_t)NREAL * H3];
__device__ float g_gi_b      [(size_t)NREAL * H3];
__device__ float g_hbuf      [(size_t)2 * MOLS * HDIM];
__device__ float g_gh        [(size_t)2 * MOLS * H3];
__device__ float g_hid       [(size_t)NREAL * HDIM];

__device__ __nv_bfloat16 g_fa_hi[(size_t)NATOM * KP_ATOM];
__device__ __nv_bfloat16 g_fa_lo[(size_t)NATOM * KP_ATOM];
__device__ __nv_bfloat16 g_fb_hi[(size_t)NBOND * KP_BOND];
__device__ __nv_bfloat16 g_fb_lo[(size_t)NBOND * KP_BOND];
__device__ __nv_bfloat16 g_tb_hi[(size_t)NBOND * KP_H];
__device__ __nv_bfloat16 g_tb_lo[(size_t)NBOND * KP_H];
__device__ __nv_bfloat16 g_nc_hi[(size_t)NATOM * KP_H3];
__device__ __nv_bfloat16 g_nc_lo[(size_t)NATOM * KP_H3];
__device__ __nv_bfloat16 g_mr_hi[(size_t)NREAL * KP_H];
__device__ __nv_bfloat16 g_mr_lo[(size_t)NREAL * KP_H];
__device__ __nv_bfloat16 g_hb_hi[(size_t)2 * MOLS * KP_H];
__device__ __nv_bfloat16 g_hb_lo[(size_t)2 * MOLS * KP_H];
__device__ __nv_bfloat16 g_o2_hi[(size_t)NREAL * KP_H2];
__device__ __nv_bfloat16 g_o2_lo[(size_t)NREAL * KP_H2];

__device__ __nv_bfloat16 g_wa_hi [(size_t)NP_H * KP_ATOM];
__device__ __nv_bfloat16 g_wa_lo [(size_t)NP_H * KP_ATOM];
__device__ __nv_bfloat16 g_wb_hi [(size_t)NP_H * KP_BOND];
__device__ __nv_bfloat16 g_wb_lo [(size_t)NP_H * KP_BOND];
__device__ __nv_bfloat16 g_wh_hi [(size_t)2 * NP_H * KP_H];
__device__ __nv_bfloat16 g_wh_lo [(size_t)2 * NP_H * KP_H];
__device__ __nv_bfloat16 g_wlr_hi[(size_t)NP_H * KP_H3];
__device__ __nv_bfloat16 g_wlr_lo[(size_t)NP_H * KP_H3];
__device__ __nv_bfloat16 g_wo_hi [(size_t)NP_H * KP_H2];
__device__ __nv_bfloat16 g_wo_lo [(size_t)NP_H * KP_H2];
__device__ __nv_bfloat16 g_gif_hi[(size_t)NP_H3 * KP_H];
__device__ __nv_bfloat16 g_gif_lo[(size_t)NP_H3 * KP_H];
__device__ __nv_bfloat16 g_gib_hi[(size_t)NP_H3 * KP_H];
__device__ __nv_bfloat16 g_gib_lo[(size_t)NP_H3 * KP_H];
__device__ __nv_bfloat16 g_ghf_hi[(size_t)NP_H3 * KP_H];
__device__ __nv_bfloat16 g_ghf_lo[(size_t)NP_H3 * KP_H];
__device__ __nv_bfloat16 g_ghb_hi[(size_t)NP_H3 * KP_H];
__device__ __nv_bfloat16 g_ghb_lo[(size_t)NP_H3 * KP_H];

// ---------------- PTX helpers (sm_80-era, legal on compute_103) ----------------
__device__ __forceinline__ uint32_t smem_to_u32(const void* p) {
    uint32_t a;
    asm("{ .reg .u64 t; cvta.to.shared.u64 t, %1; cvt.u32.u64 %0, t; }" : "=r"(a) : "l"(p));
    return a;
}
__device__ __forceinline__ void cp_async16(uint32_t saddr, const void* g, int src_bytes) {
    asm volatile("cp.async.cg.shared.global [%0], [%1], 16, %2;"
                 :: "r"(saddr), "l"(g), "r"(src_bytes) : "memory");
}
#define CP_COMMIT() asm volatile("cp.async.commit_group;" ::: "memory")
template <int N>
__device__ __forceinline__ void cp_wait() {
    asm volatile("cp.async.wait_group %0;" :: "n"(N) : "memory");
}
__device__ __forceinline__ void ldm_x4(uint32_t& r0, uint32_t& r1, uint32_t& r2, uint32_t& r3,
                                       uint32_t addr) {
    asm volatile("ldmatrix.sync.aligned.m8n8.x4.shared.b16 {%0,%1,%2,%3}, [%4];"
                 : "=r"(r0), "=r"(r1), "=r"(r2), "=r"(r3) : "r"(addr));
}
__device__ __forceinline__ void mma_bf16(float& c0, float& c1, float& c2, float& c3,
                                         uint32_t a0, uint32_t a1, uint32_t a2, uint32_t a3,
                                         uint32_t b0, uint32_t b1) {
    asm volatile("mma.sync.aligned.m16n8k16.row.col.f32.bf16.bf16.f32 "
                 "{%0,%1,%2,%3}, {%4,%5,%6,%7}, {%8,%9}, {%0,%1,%2,%3};"
                 : "+f"(c0), "+f"(c1), "+f"(c2), "+f"(c3)
                 : "r"(a0), "r"(a1), "r"(a2), "r"(a3), "r"(b0), "r"(b1));
}
__device__ __forceinline__ void bsplit(float a, __nv_bfloat16& h, __nv_bfloat16& l) {
    h = __float2bfloat16(a);
    l = __float2bfloat16(a - __bfloat162float(h));
}

// ---------------- MMA GEMM: C = relu?( add + (Ahi+Alo)@(Whi+Wlo)^T + bias ) ----------------
// A: [rows, KP] bf16 hi/lo, W: [NP, KP] bf16 hi/lo (zero-padded to wlimit rows).
// Block tile 128x128, 8 warps (2x4), warp tile 64x32, K-chunk 32, double-buffered cp.async.
// B operand is [N, K] row-major = col-major KxN -> NON-transposed ldmatrix gives the
// correct b-fragment (thread l: k=(l%4)*2+{0,1}, n=l/4).
#define GT 256
#define LDT 40            // smem tile row stride in elems (80 B)
#define TILE_B (128 * LDT * 2)   // 10240 B per tile
#define STAGE_B (4 * TILE_B)     // Ahi,Alo,Whi,Wlo
#define GSMEM (2 * STAGE_B)      // 81920 B

struct GArgs {
    const __nv_bfloat16 *Ahi, *Alo, *Whi, *Wlo, *Whi2, *Wlo2;
    const float *bias, *bias2, *addsrc;
    float *C, *C2;
    int rows, N, KPd, wlimit, rowSplit, doRelu;
};

__device__ __forceinline__ void stage_load(const GArgs& a, uint32_t sb, int stage,
                                           const __nv_bfloat16* wh, const __nv_bfloat16* wl,
                                           int row0, int col0, int k0, int tid)
{
    uint32_t base = sb + stage * STAGE_B;
    // A hi/lo: 128 rows x 4 16B-segments
    for (int u = tid; u < 512; u += GT) {
        int r = u >> 2, seg = u & 3;
        int gr = row0 + r;
        int ok = (gr < a.rows) ? 16 : 0;
        size_t go = (size_t)(ok ? gr : 0) * a.KPd + k0 + seg * 8;
        uint32_t so = (uint32_t)(r * 80 + seg * 16);
        cp_async16(base + so,              a.Ahi + go, ok);
        cp_async16(base + TILE_B + so,     a.Alo + go, ok);
    }
    // W hi/lo: 128 weight rows x 4 segments
    for (int u = tid; u < 512; u += GT) {
        int r = u >> 2, seg = u & 3;
        int gw = col0 + r;
        int ok = (gw < a.wlimit) ? 16 : 0;
        size_t go = (size_t)(ok ? gw : 0) * a.KPd + k0 + seg * 8;
        uint32_t so = (uint32_t)(r * 80 + seg * 16);
        cp_async16(base + 2 * TILE_B + so, wh + go, ok);
        cp_async16(base + 3 * TILE_B + so, wl + go, ok);
    }
}

__global__ void __launch_bounds__(GT, 1)
mma_gemm(GArgs a)
{
    extern __shared__ __align__(128) char smem[];
    uint32_t sb = smem_to_u32(smem);
    const int tid = threadIdx.x, wid = tid >> 5, lane = tid & 31;
    const int row0 = blockIdx.y * 128;
    const int col0 = blockIdx.x * 128;
    const int warp_m = (wid & 1) * 64;
    const int warp_n = (wid >> 1) * 32;

    const __nv_bfloat16* wh = (row0 >= a.rowSplit) ? a.Whi2 : a.Whi;
    const __nv_bfloat16* wl = (row0 >= a.rowSplit) ? a.Wlo2 : a.Wlo;
    const float*         bp = (row0 >= a.rowSplit) ? a.bias2 : a.bias;

    float c[4][4][4];
#pragma unroll
    for (int i = 0; i < 4; i++)
#pragma unroll
        for (int j = 0; j < 4; j++)
#pragma unroll
            for (int q = 0; q < 4; q++) c[i][j][q] = 0.f;

    // per-lane ldmatrix address pieces
    const int a_row  = warp_m + (lane & 15);          // + mt*16
    const int a_koff = (lane >> 4) << 3;              // + kstep
    const int b_nrow = warp_n + ((lane >> 4) << 3) + (lane & 7);  // + half*16
    const int b_koff = ((lane >> 3) & 1) << 3;        // + kstep

    const int NCH = a.KPd / 32;
    stage_load(a, sb, 0, wh, wl, row0, col0, 0, tid);
    CP_COMMIT();

    for (int ch = 0; ch < NCH; ch++) {
        if (ch + 1 < NCH) {
            stage_load(a, sb, (ch + 1) & 1, wh, wl, row0, col0, (ch + 1) * 32, tid);
            CP_COMMIT();
            cp_wait<1>();
        } else {
            cp_wait<0>();
        }
        __syncthreads();

        uint32_t base = sb + (ch & 1) * STAGE_B;
        uint32_t sAh = base, sAl = base + TILE_B, sWh = base + 2 * TILE_B, sWl = base + 3 * TILE_B;

#pragma unroll
        for (int ks = 0; ks < 2; ks++) {
            const int kstep = ks * 16;
            uint32_t ah[4][4], al[4][4], bh[4][2], bl[4][2];
#pragma unroll
            for (int mt = 0; mt < 4; mt++) {
                uint32_t off = (uint32_t)((a_row + mt * 16) * 80 + (kstep + a_koff) * 2);
                ldm_x4(ah[mt][0], ah[mt][1], ah[mt][2], ah[mt][3], sAh + off);
                ldm_x4(al[mt][0], al[mt][1], al[mt][2], al[mt][3], sAl + off);
            }
#pragma unroll
            for (int half = 0; half < 2; half++) {
                uint32_t off = (uint32_t)((b_nrow + half * 16) * 80 + (kstep + b_koff) * 2);
                // NON-trans: B stored [N,K] row-major == col-major KxN as mma expects
                ldm_x4(bh[half*2][0], bh[half*2][1], bh[half*2+1][0], bh[half*2+1][1], sWh + off);
                ldm_x4(bl[half*2][0], bl[half*2][1], bl[half*2+1][0], bl[half*2+1][1], sWl + off);
            }
#pragma unroll
            for (int mt = 0; mt < 4; mt++)
#pragma unroll
                for (int nt = 0; nt < 4; nt++) {
                    mma_bf16(c[mt][nt][0], c[mt][nt][1], c[mt][nt][2], c[mt][nt][3],
                             ah[mt][0], ah[mt][1], ah[mt][2], ah[mt][3], bh[nt][0], bh[nt][1]);
                    mma_bf16(c[mt][nt][0], c[mt][nt][1], c[mt][nt][2], c[mt][nt][3],
                             ah[mt][0], ah[mt][1], ah[mt][2], ah[mt][3], bl[nt][0], bl[nt][1]);
                    mma_bf16(c[mt][nt][0], c[mt][nt][1], c[mt][nt][2], c[mt][nt][3],
                             al[mt][0], al[mt][1], al[mt][2], al[mt][3], bh[nt][0], bh[nt][1]);
                }
        }
        __syncthreads();
    }

    // epilogue from registers
#pragma unroll
    for (int mt = 0; mt < 4; mt++) {
        int gr0 = row0 + warp_m + mt * 16 + (lane >> 2);
#pragma unroll
        for (int nt = 0; nt < 4; nt++) {
            int gc = col0 + warp_n + nt * 8 + (lane & 3) * 2;
            float b0 = 0.f, b1 = 0.f;
            if (bp) {
                if (gc < a.N)     b0 = bp[gc];
                if (gc + 1 < a.N) b1 = bp[gc + 1];
            }
#pragma unroll
            for (int hh = 0; hh < 2; hh++) {
                int gr = gr0 + hh * 8;
                if (gr >= a.rows) continue;
                float v0 = c[mt][nt][hh * 2 + 0] + b0;
                float v1 = c[mt][nt][hh * 2 + 1] + b1;
                size_t o = (size_t)gr * a.N + gc;
                if (a.addsrc) {
                    if (gc < a.N)     v0 += a.addsrc[o];
                    if (gc + 1 < a.N) v1 += a.addsrc[o + 1];
                }
                if (a.doRelu) { v0 = fmaxf(v0, 0.f); v1 = fmaxf(v1, 0.f); }
                if (gc < a.N)     { a.C[o] = v0;     if (a.C2) a.C2[o] = v0; }
                if (gc + 1 < a.N) { a.C[o + 1] = v1; if (a.C2) a.C2[o + 1] = v1; }
            }
        }
    }
}

// ---------------- conversion / elementwise kernels ----------------
__global__ void conv_split(const float* __restrict__ src, __nv_bfloat16* __restrict__ hi,
                           __nv_bfloat16* __restrict__ lo, int Nn, int Kk, long long NPd, int KPd)
{
    long long total = NPd * (long long)KPd;
    for (long long e = blockIdx.x * (long long)blockDim.x + threadIdx.x; e < total;
         e += (long long)gridDim.x * blockDim.x) {
        int n = (int)(e / KPd), k = (int)(e % KPd);
        float v = (n < Nn && k < Kk) ? src[(size_t)n * Kk + k] : 0.f;
        __nv_bfloat16 h, l; bsplit(v, h, l);
        hi[e] = h; lo[e] = l;
    }
}

__global__ void agg_update_kernel(const int* __restrict__ a2b, const float* __restrict__ mb,
                                  float* __restrict__ ma)
{
    int i = blockIdx.x;
    __shared__ int idx[MAXNB];
    if (threadIdx.x < MAXNB) idx[threadIdx.x] = a2b[(size_t)i * MAXNB + threadIdx.x];
    __syncthreads();
    int h = threadIdx.x;
    if (h < HDIM) {
        float s = 0.f, m = -INFINITY;
#pragma unroll
        for (int j = 0; j < MAXNB; j++) {
            float v = mb[(size_t)idx[j] * HDIM + h];
            s += v; m = fmaxf(m, v);
        }
        ma[(size_t)i * HDIM + h] += s * m;
    }
}

__global__ void bond_gather_b(const int* __restrict__ b2a, const int* __restrict__ b2revb,
                              const float* __restrict__ ma, const float* __restrict__ mb,
                              __nv_bfloat16* __restrict__ th, __nv_bfloat16* __restrict__ tl)
{
    int e = blockIdx.x;
    __shared__ int sa, sr;
    if (threadIdx.x == 0) { sa = b2a[e]; sr = b2revb[e]; }
    __syncthreads();
    int h = threadIdx.x;
    __nv_bfloat16 z = __float2bfloat16(0.f);
    if (h < HDIM) {
        float v = ma[(size_t)sa * HDIM + h] - mb[(size_t)sr * HDIM + h];
        __nv_bfloat16 x, y; bsplit(v, x, y);
        th[(size_t)e * KP_H + h] = x; tl[(size_t)e * KP_H + h] = y;
    } else if (h < KP_H) {
        th[(size_t)e * KP_H + h] = z; tl[(size_t)e * KP_H + h] = z;
    }
}

__global__ void agg_final_b(const int* __restrict__ a2b, const float* __restrict__ mb,
                            const float* __restrict__ ma, const float* __restrict__ ia,
                            __nv_bfloat16* __restrict__ nh, __nv_bfloat16* __restrict__ nl)
{
    int i = blockIdx.x;
    __shared__ int idx[MAXNB];
    if (threadIdx.x < MAXNB) idx[threadIdx.x] = a2b[(size_t)i * MAXNB + threadIdx.x];
    __syncthreads();
    int h = threadIdx.x;
    size_t base = (size_t)i * KP_H3;
    __nv_bfloat16 z = __float2bfloat16(0.f);
    if (h < HDIM) {
        float s = 0.f, m = -INFINITY;
#pragma unroll
        for (int j = 0; j < MAXNB; j++) {
            float v = mb[(size_t)idx[j] * HDIM + h];
            s += v; m = fmaxf(m, v);
        }
        __nv_bfloat16 x, y;
        bsplit(s * m, x, y);                          nh[base + h] = x;        nl[base + h] = y;
        bsplit(ma[(size_t)i * HDIM + h], x, y);       nh[base + 300 + h] = x;  nl[base + 300 + h] = y;
        bsplit(ia[(size_t)i * HDIM + h], x, y);       nh[base + 600 + h] = x;  nl[base + 600 + h] = y;
    } else if (h < 320) {
        int p = h - 300;
        nh[base + 900 + p] = z; nl[base + 900 + p] = z;
        nh[base + 920 + p] = z; nl[base + 920 + p] = z;
        nh[base + 940 + p] = z; nl[base + 940 + p] = z;
    }
}

__global__ void h0_msg_b(const float* __restrict__ node, float* __restrict__ hbuf,
                         __nv_bfloat16* __restrict__ hbh, __nv_bfloat16* __restrict__ hbl,
                         __nv_bfloat16* __restrict__ mrh, __nv_bfloat16* __restrict__ mrl)
{
    int m = blockIdx.x;
    int h = threadIdx.x;
    __nv_bfloat16 z = __float2bfloat16(0.f);
    if (h < HDIM) {
        float mx = -INFINITY;
        for (int a = 0; a < APM; a++) {
            float v = node[(size_t)(1 + m * APM + a) * HDIM + h];
            mx = fmaxf(mx, v);
            __nv_bfloat16 x, y; bsplit(fmaxf(v, 0.f), x, y);
            mrh[(size_t)(m * APM + a) * KP_H + h] = x;
            mrl[(size_t)(m * APM + a) * KP_H + h] = y;
        }
        hbuf[(size_t)m * HDIM + h] = mx;
        hbuf[(size_t)(MOLS + m) * HDIM + h] = mx;
        __nv_bfloat16 x, y; bsplit(mx, x, y);
        hbh[(size_t)m * KP_H + h] = x;           hbl[(size_t)m * KP_H + h] = y;
        hbh[(size_t)(MOLS + m) * KP_H + h] = x;  hbl[(size_t)(MOLS + m) * KP_H + h] = y;
    } else if (h < KP_H) {
        for (int a = 0; a < APM; a++) {
            mrh[(size_t)(m * APM + a) * KP_H + h] = z;
            mrl[(size_t)(m * APM + a) * KP_H + h] = z;
        }
        hbh[(size_t)m * KP_H + h] = z;           hbl[(size_t)m * KP_H + h] = z;
        hbh[(size_t)(MOLS + m) * KP_H + h] = z;  hbl[(size_t)(MOLS + m) * KP_H + h] = z;
    }
}

__global__ void pad_o2(__nv_bfloat16* __restrict__ oh, __nv_bfloat16* __restrict__ ol)
{
    __nv_bfloat16 z = __float2bfloat16(0.f);
    long long total = (long long)NREAL * 40;
    for (long long e = blockIdx.x * (long long)blockDim.x + threadIdx.x; e < total;
         e += (long long)gridDim.x * blockDim.x) {
        long long r = e / 40; int c = 600 + (int)(e % 40);
        oh[r * KP_H2 + c] = z; ol[r * KP_H2 + c] = z;
    }
}

__global__ void gru_gate(const float* __restrict__ gi_f, const float* __restrict__ gi_b,
                         const float* __restrict__ gh, float* __restrict__ hbuf,
                         __nv_bfloat16* __restrict__ hbh, __nv_bfloat16* __restrict__ hbl,
                         __nv_bfloat16* __restrict__ o2h, __nv_bfloat16* __restrict__ o2l, int t)
{
    int idx = blockIdx.x * blockDim.x + threadIdx.x;
    if (idx >= 2 * MOLS * HDIM) return;
    int mrow = idx / HDIM, h = idx % HDIM;
    bool bwd = mrow >= MOLS;
    int m = bwd ? (mrow - MOLS) : mrow;
    int a = bwd ? (APM - 1 - t) : t;
    int xrow = m * APM + a;
    const float* gi = bwd ? gi_b : gi_f;
    size_t gib = (size_t)xrow * H3, ghb = (size_t)mrow * H3;
    float ir = gi[gib + h], iz = gi[gib + HDIM + h], inn = gi[gib + 2 * HDIM + h];
    float hr = gh[ghb + h], hz = gh[ghb + HDIM + h], hn = gh[ghb + 2 * HDIM + h];
    float hp = hbuf[(size_t)mrow * HDIM + h];
    float r = 1.f / (1.f + expf(-(ir + hr)));
    float z = 1.f / (1.f + expf(-(iz + hz)));
    float n = tanhf(inn + r * hn);
    float hnew = (1.f - z) * n + z * hp;
    hbuf[(size_t)mrow * HDIM + h] = hnew;
    __nv_bfloat16 x, y; bsplit(hnew, x, y);
    hbh[(size_t)mrow * KP_H + h] = x; hbl[(size_t)mrow * KP_H + h] = y;
    int cc = (bwd ? HDIM : 0) + h;
    o2h[(size_t)xrow * KP_H2 + cc] = x; o2l[(size_t)xrow * KP_H2 + cc] = y;
}

__global__ void mean_kernel(const float* __restrict__ hid, float* __restrict__ out)
{
    int m = blockIdx.x, h = threadIdx.x;
    if (h >= HDIM) return;
    float s = 0.f;
    for (int a = 0; a < APM; a++) s += hid[(size_t)(m * APM + a) * HDIM + h];
    out[(size_t)m * HDIM + h] = s * (1.f / (float)APM);
}

// ---------------- host ----------------
typedef __nv_bfloat16 bf16;

static inline void tcg(const bf16* Ah, const bf16* Al, int KPd, int wlimit,
                       const bf16* Wh, const bf16* Wl, const bf16* Wh2, const bf16* Wl2, int split,
                       const float* b, const float* b2, const float* add,
                       float* C, float* C2, int rows, int N, int relu)
{
    GArgs a;
    a.Ahi = Ah; a.Alo = Al; a.Whi = Wh; a.Wlo = Wl; a.Whi2 = Wh2; a.Wlo2 = Wl2;
    a.bias = b; a.bias2 = b2; a.addsrc = add; a.C = C; a.C2 = C2;
    a.rows = rows; a.N = N; a.KPd = KPd; a.wlimit = wlimit; a.rowSplit = split; a.doRelu = relu;
    dim3 grid((N + 127) / 128, (rows + 127) / 128);
    mma_gemm<<<grid, GT, GSMEM>>>(a);
}

static inline void conv(const float* s, bf16* h, bf16* l, int Nn, int Kk, long long NPd, int KPd)
{
    long long total = NPd * (long long)KPd;
    int blocks = (int)((total + 255) / 256);
    if (blocks > 8192) blocks = 8192;
    conv_split<<<blocks, 256>>>(s, h, l, Nn, Kk, NPd, KPd);
}

extern "C" void kernel_launch(void* const* d_in, const int* in_sizes, int n_in,
                              void* d_out, int out_size)
{
    (void)out_size;
    const float* f_atoms = (const float*)d_in[0];
    const float* f_bonds = (const float*)d_in[1];
    const int*   a2b     = (const int*)d_in[2];
    const int*   b2a     = (const int*)d_in[3];
    const int*   b2revb  = (const int*)d_in[4];

    int wi = 5;
    for (int j = 5; j < n_in; j++) if (in_sizes[j] == HDIM * AFD) { wi = j; break; }
    const float* W_i_atom = (const float*)d_in[wi + 0];
    const float* W_i_bond = (const float*)d_in[wi + 1];
    const float* W_h      = (const float*)d_in[wi + 2];
    const float* lr_W     = (const float*)d_in[wi + 3];
    const float* W_o_W    = (const float*)d_in[wi + 4];
    const float* W_o_b    = (const float*)d_in[wi + 5];
    const float* gWih_f   = (const float*)d_in[wi + 6];
    const float* gWhh_f   = (const float*)d_in[wi + 7];
    const float* gbih_f   = (const float*)d_in[wi + 8];
    const float* gbhh_f   = (const float*)d_in[wi + 9];
    const float* gWih_b   = (const float*)d_in[wi + 10];
    const float* gWhh_b   = (const float*)d_in[wi + 11];
    const float* gbih_b   = (const float*)d_in[wi + 12];
    const float* gbhh_b   = (const float*)d_in[wi + 13];
    float* out = (float*)d_out;

    cudaFuncSetAttribute(mma_gemm, cudaFuncAttributeMaxDynamicSharedMemorySize, GSMEM);

#define SYM(p, s) float* p; cudaGetSymbolAddress((void**)&p, s)
#define SYB(p, s) bf16* p; cudaGetSymbolAddress((void**)&p, s)
    SYM(input_atom, g_input_atom); SYM(input_bond, g_input_bond);
    SYM(msg_atom, g_msg_atom);     SYM(msg_bond, g_msg_bond);
    SYM(node, g_node);             SYM(gi_f, g_gi_f); SYM(gi_b, g_gi_b);
    SYM(hbuf, g_hbuf);             SYM(gh, g_gh);     SYM(hid, g_hid);
    SYB(fa_hi, g_fa_hi); SYB(fa_lo, g_fa_lo); SYB(fb_hi, g_fb_hi); SYB(fb_lo, g_fb_lo);
    SYB(tb_hi, g_tb_hi); SYB(tb_lo, g_tb_lo); SYB(nc_hi, g_nc_hi); SYB(nc_lo, g_nc_lo);
    SYB(mr_hi, g_mr_hi); SYB(mr_lo, g_mr_lo); SYB(hb_hi, g_hb_hi); SYB(hb_lo, g_hb_lo);
    SYB(o2_hi, g_o2_hi); SYB(o2_lo, g_o2_lo);
    SYB(wa_hi, g_wa_hi); SYB(wa_lo, g_wa_lo); SYB(wb_hi, g_wb_hi); SYB(wb_lo, g_wb_lo);
    SYB(wh_hi, g_wh_hi); SYB(wh_lo, g_wh_lo); SYB(wlr_hi, g_wlr_hi); SYB(wlr_lo, g_wlr_lo);
    SYB(wo_hi, g_wo_hi); SYB(wo_lo, g_wo_lo);
    SYB(gif_hi, g_gif_hi); SYB(gif_lo, g_gif_lo); SYB(gib_hi, g_gib_hi); SYB(gib_lo, g_gib_lo);
    SYB(ghf_hi, g_ghf_hi); SYB(ghf_lo, g_ghf_lo); SYB(ghb_hi, g_ghb_hi); SYB(ghb_lo, g_ghb_lo);
#undef SYM
#undef SYB

    const int EB = 320;

    // 0) conversions (inputs + weights) and pad init
    conv(f_atoms, fa_hi, fa_lo, NATOM, AFD, NATOM, KP_ATOM);
    conv(f_bonds, fb_hi, fb_lo, NBOND, BFD, NBOND, KP_BOND);
    conv(W_i_atom, wa_hi, wa_lo, HDIM, AFD, NP_H, KP_ATOM);
    conv(W_i_bond, wb_hi, wb_lo, HDIM, BFD, NP_H, KP_BOND);
    conv(W_h,                     wh_hi,                     wh_lo,                     HDIM, HDIM, NP_H, KP_H);
    conv(W_h + (size_t)HDIM*HDIM, wh_hi + (size_t)NP_H*KP_H, wh_lo + (size_t)NP_H*KP_H, HDIM, HDIM, NP_H, KP_H);
    conv(lr_W,   wlr_hi, wlr_lo, HDIM, H3, NP_H,  KP_H3);
    conv(W_o_W,  wo_hi,  wo_lo,  HDIM, H2, NP_H,  KP_H2);
    conv(gWih_f, gif_hi, gif_lo, H3, HDIM, NP_H3, KP_H);
    conv(gWih_b, gib_hi, gib_lo, H3, HDIM, NP_H3, KP_H);
    conv(gWhh_f, ghf_hi, ghf_lo, H3, HDIM, NP_H3, KP_H);
    conv(gWhh_b, ghb_hi, ghb_lo, H3, HDIM, NP_H3, KP_H);
    pad_o2<<<4096, 256>>>(o2_hi, o2_lo);

    // 1) input projections (dup-write into message buffers)
    tcg(fa_hi, fa_lo, KP_ATOM, NP_H, wa_hi, wa_lo, nullptr, nullptr, INT_MAX,
        nullptr, nullptr, nullptr, input_atom, msg_atom, NATOM, HDIM, 1);
    tcg(fb_hi, fb_lo, KP_BOND, NP_H, wb_hi, wb_lo, nullptr, nullptr, INT_MAX,
        nullptr, nullptr, nullptr, input_bond, msg_bond, NBOND, HDIM, 1);

    // 2) message-passing depth loop
    for (int d = 0; d < 2; d++) {
        agg_update_kernel<<<NATOM, EB>>>(a2b, msg_bond, msg_atom);
        bond_gather_b<<<NBOND, EB>>>(b2a, b2revb, msg_atom, msg_bond, tb_hi, tb_lo);
        tcg(tb_hi, tb_lo, KP_H, NP_H,
            wh_hi + (size_t)d * NP_H * KP_H, wh_lo + (size_t)d * NP_H * KP_H,
            nullptr, nullptr, INT_MAX, nullptr, nullptr, input_bond,
            msg_bond, nullptr, NBOND, HDIM, 1);
    }

    // 3) final agg + concat + lr GEMM
    agg_final_b<<<NATOM, EB>>>(a2b, msg_bond, msg_atom, input_atom, nc_hi, nc_lo);
    tcg(nc_hi, nc_lo, KP_H3, NP_H, wlr_hi, wlr_lo, nullptr, nullptr, INT_MAX,
        nullptr, nullptr, nullptr, node, nullptr, NATOM, HDIM, 0);

    // 4) h0 + msgrelu
    h0_msg_b<<<MOLS, EB>>>(node, hbuf, hb_hi, hb_lo, mr_hi, mr_lo);

    // 5) GRU input gates
    tcg(mr_hi, mr_lo, KP_H, NP_H3, gif_hi, gif_lo, nullptr, nullptr, INT_MAX,
        gbih_f, nullptr, nullptr, gi_f, nullptr, NREAL, H3, 0);
    tcg(mr_hi, mr_lo, KP_H, NP_H3, gib_hi, gib_lo, nullptr, nullptr, INT_MAX,
        gbih_b, nullptr, nullptr, gi_b, nullptr, NREAL, H3, 0);

    // 6) GRU recurrence (fused fwd/bwd via rowSplit)
    for (int t = 0; t < APM; t++) {
        tcg(hb_hi, hb_lo, KP_H, NP_H3, ghf_hi, ghf_lo, ghb_hi, ghb_lo, MOLS,
            gbhh_f, gbhh_b, nullptr, gh, nullptr, 2 * MOLS, H3, 0);
        gru_gate<<<(2 * MOLS * HDIM + 255) / 256, 256>>>(
            gi_f, gi_b, gh, hbuf, hb_hi, hb_lo, o2_hi, o2_lo, t);
    }

    // 7) output projection + mean
    tcg(o2_hi, o2_lo, KP_H2, NP_H, wo_hi, wo_lo, nullptr, nullptr, INT_MAX,
        W_o_b, nullptr, nullptr, hid, nullptr, NREAL, HDIM, 1);
    mean_kernel<<<MOLS, EB>>>(hid, out);
}

// round 17
// speedup vs baseline: 1.0496x; 1.0496x over previous
#include <cuda_runtime.h>
#include <cuda_bf16.h>
#include <math.h>
#include <limits.h>
#include <stdint.h>

// ---------------- problem constants ----------------
#define NATOM  32769
#define NBOND  131073
#define NREAL  32768
#define HDIM   300
#define H3     900
#define H2     600
#define MOLS   512
#define APM    64
#define MAXNB  6
#define AFD    133
#define BFD    147

#define KP_ATOM 192
#define KP_BOND 192
#define KP_H    320
#define KP_H3   960
#define KP_H2   640
#define NP_H    320
#define NP_H3   960

// ---------------- device scratch ----------------
__device__ float g_input_atom[(size_t)NATOM * HDIM];
__device__ float g_input_bond[(size_t)NBOND * HDIM];
__device__ float g_msg_atom  [(size_t)NATOM * HDIM];
__device__ float g_msg_bond  [(size_t)NBOND * HDIM];
__device__ float g_node      [(size_t)NATOM * HDIM];
__device__ float g_gi_f      [(size_t)NREAL * H3];   // gate-interleaved cols
__device__ float g_gi_b      [(size_t)NREAL * H3];
__device__ float g_hbuf      [(size_t)2 * 1024 * HDIM];  // double-buffered
__device__ float g_hid       [(size_t)NREAL * HDIM];

__device__ __nv_bfloat16 g_fa_hi[(size_t)NATOM * KP_ATOM];
__device__ __nv_bfloat16 g_fa_lo[(size_t)NATOM * KP_ATOM];
__device__ __nv_bfloat16 g_fb_hi[(size_t)NBOND * KP_BOND];
__device__ __nv_bfloat16 g_fb_lo[(size_t)NBOND * KP_BOND];
__device__ __nv_bfloat16 g_tb_hi[(size_t)NBOND * KP_H];
__device__ __nv_bfloat16 g_tb_lo[(size_t)NBOND * KP_H];
__device__ __nv_bfloat16 g_nc_hi[(size_t)NATOM * KP_H3];
__device__ __nv_bfloat16 g_nc_lo[(size_t)NATOM * KP_H3];
__device__ __nv_bfloat16 g_mr_hi[(size_t)NREAL * KP_H];
__device__ __nv_bfloat16 g_mr_lo[(size_t)NREAL * KP_H];
__device__ __nv_bfloat16 g_hb_hi[(size_t)2 * 1024 * KP_H];  // double-buffered
__device__ __nv_bfloat16 g_hb_lo[(size_t)2 * 1024 * KP_H];
__device__ __nv_bfloat16 g_o2_hi[(size_t)NREAL * KP_H2];
__device__ __nv_bfloat16 g_o2_lo[(size_t)NREAL * KP_H2];

__device__ __nv_bfloat16 g_wa_hi [(size_t)NP_H * KP_ATOM];
__device__ __nv_bfloat16 g_wa_lo [(size_t)NP_H * KP_ATOM];
__device__ __nv_bfloat16 g_wb_hi [(size_t)NP_H * KP_BOND];
__device__ __nv_bfloat16 g_wb_lo [(size_t)NP_H * KP_BOND];
__device__ __nv_bfloat16 g_wh_hi [(size_t)2 * NP_H * KP_H];
__device__ __nv_bfloat16 g_wh_lo [(size_t)2 * NP_H * KP_H];
__device__ __nv_bfloat16 g_wlr_hi[(size_t)NP_H * KP_H3];
__device__ __nv_bfloat16 g_wlr_lo[(size_t)NP_H * KP_H3];
__device__ __nv_bfloat16 g_wo_hi [(size_t)NP_H * KP_H2];
__device__ __nv_bfloat16 g_wo_lo [(size_t)NP_H * KP_H2];
// gate-interleaved GRU weights [960][320]
__device__ __nv_bfloat16 g_gif_hi[(size_t)NP_H3 * KP_H];
__device__ __nv_bfloat16 g_gif_lo[(size_t)NP_H3 * KP_H];
__device__ __nv_bfloat16 g_gib_hi[(size_t)NP_H3 * KP_H];
__device__ __nv_bfloat16 g_gib_lo[(size_t)NP_H3 * KP_H];
__device__ __nv_bfloat16 g_ghf_hi[(size_t)NP_H3 * KP_H];
__device__ __nv_bfloat16 g_ghf_lo[(size_t)NP_H3 * KP_H];
__device__ __nv_bfloat16 g_ghb_hi[(size_t)NP_H3 * KP_H];
__device__ __nv_bfloat16 g_ghb_lo[(size_t)NP_H3 * KP_H];

// ---------------- PTX helpers ----------------
__device__ __forceinline__ uint32_t smem_to_u32(const void* p) {
    uint32_t a;
    asm("{ .reg .u64 t; cvta.to.shared.u64 t, %1; cvt.u32.u64 %0, t; }" : "=r"(a) : "l"(p));
    return a;
}
__device__ __forceinline__ void cp_async16(uint32_t saddr, const void* g, int src_bytes) {
    asm volatile("cp.async.cg.shared.global [%0], [%1], 16, %2;"
                 :: "r"(saddr), "l"(g), "r"(src_bytes) : "memory");
}
#define CP_COMMIT() asm volatile("cp.async.commit_group;" ::: "memory")
template <int N>
__device__ __forceinline__ void cp_wait() {
    asm volatile("cp.async.wait_group %0;" :: "n"(N) : "memory");
}
__device__ __forceinline__ void ldm_x4(uint32_t& r0, uint32_t& r1, uint32_t& r2, uint32_t& r3,
                                       uint32_t addr) {
    asm volatile("ldmatrix.sync.aligned.m8n8.x4.shared.b16 {%0,%1,%2,%3}, [%4];"
                 : "=r"(r0), "=r"(r1), "=r"(r2), "=r"(r3) : "r"(addr));
}
__device__ __forceinline__ void mma_bf16(float& c0, float& c1, float& c2, float& c3,
                                         uint32_t a0, uint32_t a1, uint32_t a2, uint32_t a3,
                                         uint32_t b0, uint32_t b1) {
    asm volatile("mma.sync.aligned.m16n8k16.row.col.f32.bf16.bf16.f32 "
                 "{%0,%1,%2,%3}, {%4,%5,%6,%7}, {%8,%9}, {%0,%1,%2,%3};"
                 : "+f"(c0), "+f"(c1), "+f"(c2), "+f"(c3)
                 : "r"(a0), "r"(a1), "r"(a2), "r"(a3), "r"(b0), "r"(b1));
}
__device__ __forceinline__ void bsplit(float a, __nv_bfloat16& h, __nv_bfloat16& l) {
    h = __float2bfloat16(a);
    l = __float2bfloat16(a - __bfloat162float(h));
}

// ---------------- generic MMA GEMM (unchanged from passing R14) ----------------
#define GT 256
#define LDT 40
#define TILE_B (128 * LDT * 2)
#define STAGE_B (4 * TILE_B)
#define GSMEM (2 * STAGE_B)

struct GArgs {
    const __nv_bfloat16 *Ahi, *Alo, *Whi, *Wlo, *Whi2, *Wlo2;
    const float *bias, *bias2, *addsrc;
    float *C, *C2;
    int rows, N, KPd, wlimit, rowSplit, doRelu;
};

__device__ __forceinline__ void stage_load(const GArgs& a, uint32_t sb, int stage,
                                           const __nv_bfloat16* wh, const __nv_bfloat16* wl,
                                           int row0, int col0, int k0, int tid)
{
    uint32_t base = sb + stage * STAGE_B;
    for (int u = tid; u < 512; u += GT) {
        int r = u >> 2, seg = u & 3;
        int gr = row0 + r;
        int ok = (gr < a.rows) ? 16 : 0;
        size_t go = (size_t)(ok ? gr : 0) * a.KPd + k0 + seg * 8;
        uint32_t so = (uint32_t)(r * 80 + seg * 16);
        cp_async16(base + so,          a.Ahi + go, ok);
        cp_async16(base + TILE_B + so, a.Alo + go, ok);
    }
    for (int u = tid; u < 512; u += GT) {
        int r = u >> 2, seg = u & 3;
        int gw = col0 + r;
        int ok = (gw < a.wlimit) ? 16 : 0;
        size_t go = (size_t)(ok ? gw : 0) * a.KPd + k0 + seg * 8;
        uint32_t so = (uint32_t)(r * 80 + seg * 16);
        cp_async16(base + 2 * TILE_B + so, wh + go, ok);
        cp_async16(base + 3 * TILE_B + so, wl + go, ok);
    }
}

__global__ void __launch_bounds__(GT, 1)
mma_gemm(GArgs a)
{
    extern __shared__ __align__(128) char smem[];
    uint32_t sb = smem_to_u32(smem);
    const int tid = threadIdx.x, wid = tid >> 5, lane = tid & 31;
    const int row0 = blockIdx.y * 128;
    const int col0 = blockIdx.x * 128;
    const int warp_m = (wid & 1) * 64;
    const int warp_n = (wid >> 1) * 32;

    const __nv_bfloat16* wh = (row0 >= a.rowSplit) ? a.Whi2 : a.Whi;
    const __nv_bfloat16* wl = (row0 >= a.rowSplit) ? a.Wlo2 : a.Wlo;
    const float*         bp = (row0 >= a.rowSplit) ? a.bias2 : a.bias;

    float c[4][4][4];
#pragma unroll
    for (int i = 0; i < 4; i++)
#pragma unroll
        for (int j = 0; j < 4; j++)
#pragma unroll
            for (int q = 0; q < 4; q++) c[i][j][q] = 0.f;

    const int a_row  = warp_m + (lane & 15);
    const int a_koff = (lane >> 4) << 3;
    const int b_nrow = warp_n + ((lane >> 4) << 3) + (lane & 7);
    const int b_koff = ((lane >> 3) & 1) << 3;

    const int NCH = a.KPd / 32;
    stage_load(a, sb, 0, wh, wl, row0, col0, 0, tid);
    CP_COMMIT();

    for (int ch = 0; ch < NCH; ch++) {
        if (ch + 1 < NCH) {
            stage_load(a, sb, (ch + 1) & 1, wh, wl, row0, col0, (ch + 1) * 32, tid);
            CP_COMMIT();
            cp_wait<1>();
        } else {
            cp_wait<0>();
        }
        __syncthreads();

        uint32_t base = sb + (ch & 1) * STAGE_B;
        uint32_t sAh = base, sAl = base + TILE_B, sWh = base + 2 * TILE_B, sWl = base + 3 * TILE_B;

#pragma unroll
        for (int ks = 0; ks < 2; ks++) {
            const int kstep = ks * 16;
            uint32_t ah[4][4], al[4][4], bh[4][2], bl[4][2];
#pragma unroll
            for (int mt = 0; mt < 4; mt++) {
                uint32_t off = (uint32_t)((a_row + mt * 16) * 80 + (kstep + a_koff) * 2);
                ldm_x4(ah[mt][0], ah[mt][1], ah[mt][2], ah[mt][3], sAh + off);
                ldm_x4(al[mt][0], al[mt][1], al[mt][2], al[mt][3], sAl + off);
            }
#pragma unroll
            for (int half = 0; half < 2; half++) {
                uint32_t off = (uint32_t)((b_nrow + half * 16) * 80 + (kstep + b_koff) * 2);
                ldm_x4(bh[half*2][0], bh[half*2][1], bh[half*2+1][0], bh[half*2+1][1], sWh + off);
                ldm_x4(bl[half*2][0], bl[half*2][1], bl[half*2+1][0], bl[half*2+1][1], sWl + off);
            }
#pragma unroll
            for (int mt = 0; mt < 4; mt++)
#pragma unroll
                for (int nt = 0; nt < 4; nt++) {
                    mma_bf16(c[mt][nt][0], c[mt][nt][1], c[mt][nt][2], c[mt][nt][3],
                             ah[mt][0], ah[mt][1], ah[mt][2], ah[mt][3], bh[nt][0], bh[nt][1]);
                    mma_bf16(c[mt][nt][0], c[mt][nt][1], c[mt][nt][2], c[mt][nt][3],
                             ah[mt][0], ah[mt][1], ah[mt][2], ah[mt][3], bl[nt][0], bl[nt][1]);
                    mma_bf16(c[mt][nt][0], c[mt][nt][1], c[mt][nt][2], c[mt][nt][3],
                             al[mt][0], al[mt][1], al[mt][2], al[mt][3], bh[nt][0], bh[nt][1]);
                }
        }
        __syncthreads();
    }

#pragma unroll
    for (int mt = 0; mt < 4; mt++) {
        int gr0 = row0 + warp_m + mt * 16 + (lane >> 2);
#pragma unroll
        for (int nt = 0; nt < 4; nt++) {
            int gc = col0 + warp_n + nt * 8 + (lane & 3) * 2;
            float b0 = 0.f, b1 = 0.f;
            if (bp) {
                if (gc < a.N)     b0 = bp[gc];
                if (gc + 1 < a.N) b1 = bp[gc + 1];
            }
#pragma unroll
            for (int hh = 0; hh < 2; hh++) {
                int gr = gr0 + hh * 8;
                if (gr >= a.rows) continue;
                float v0 = c[mt][nt][hh * 2 + 0] + b0;
                float v1 = c[mt][nt][hh * 2 + 1] + b1;
                size_t o = (size_t)gr * a.N + gc;
                if (a.addsrc) {
                    if (gc < a.N)     v0 += a.addsrc[o];
                    if (gc + 1 < a.N) v1 += a.addsrc[o + 1];
                }
                if (a.doRelu) { v0 = fmaxf(v0, 0.f); v1 = fmaxf(v1, 0.f); }
                if (gc < a.N)     { a.C[o] = v0;     if (a.C2) a.C2[o] = v0; }
                if (gc + 1 < a.N) { a.C[o + 1] = v1; if (a.C2) a.C2[o + 1] = v1; }
            }
        }
    }
}

// ---------------- fused GRU step: gh GEMM + gate math in one kernel ----------------
// rows = 1024 (fwd 512 | bwd 512), W gate-interleaved [960][320], tile 64x96, grid 10x16.
#define S_AT (64 * 80)               // 5120 B per A tile (hi or lo)
#define S_WT (96 * 80)               // 7680 B per W tile
#define S_STAGE (2 * S_AT + 2 * S_WT)  // 25600
#define S_SMEM (2 * S_STAGE)           // 51200

__global__ void __launch_bounds__(256, 1)
gru_step(const __nv_bfloat16* __restrict__ hbh_cur, const __nv_bfloat16* __restrict__ hbl_cur,
         const __nv_bfloat16* __restrict__ whf_hi, const __nv_bfloat16* __restrict__ whf_lo,
         const __nv_bfloat16* __restrict__ whb_hi, const __nv_bfloat16* __restrict__ whb_lo,
         const float* __restrict__ gi_f, const float* __restrict__ gi_b,
         const float* __restrict__ gbih_f, const float* __restrict__ gbhh_f,
         const float* __restrict__ gbih_b, const float* __restrict__ gbhh_b,
         const float* __restrict__ hbuf_cur, float* __restrict__ hbuf_nxt,
         __nv_bfloat16* __restrict__ hbh_nxt, __nv_bfloat16* __restrict__ hbl_nxt,
         __nv_bfloat16* __restrict__ o2h, __nv_bfloat16* __restrict__ o2l, int t)
{
    extern __shared__ __align__(128) char smem[];
    uint32_t sb = smem_to_u32(smem);
    const int tid = threadIdx.x, wid = tid >> 5, lane = tid & 31;
    const int row0 = blockIdx.y * 64;
    const int col0 = blockIdx.x * 96;         // interleaved col base
    const int hbase = blockIdx.x * 32;        // hidden-unit base
    const bool bwdW = row0 >= 512;

    const __nv_bfloat16* wh = bwdW ? whb_hi : whf_hi;
    const __nv_bfloat16* wl = bwdW ? whb_lo : whf_lo;

    // warp layout: 4x2 -> warp tile 16 rows x 48 cols (1 m16, 6 n8)
    const int warp_m = (wid & 3) * 16;
    const int warp_n = (wid >> 2) * 48;

    float c[6][4];
#pragma unroll
    for (int i = 0; i < 6; i++)
#pragma unroll
        for (int q = 0; q < 4; q++) c[i][q] = 0.f;

    const int a_row  = warp_m + (lane & 15);
    const int a_koff = (lane >> 4) << 3;
    const int b_base = ((lane >> 4) << 3) + (lane & 7);
    const int b_koff = ((lane >> 3) & 1) << 3;

    // stage loader
    auto sload = [&](int stage, int k0) {
        uint32_t base = sb + stage * S_STAGE;
        {   // A: 64 rows x 4 segs = 256 -> one per thread
            int r = tid >> 2, seg = tid & 3;
            size_t go = (size_t)(row0 + r) * KP_H + k0 + seg * 8;
            uint32_t so = (uint32_t)(r * 80 + seg * 16);
            cp_async16(base + so,        hbh_cur + go, 16);
            cp_async16(base + S_AT + so, hbl_cur + go, 16);
        }
        for (int u = tid; u < 384; u += 256) {  // W: 96 rows x 4 segs
            int r = u >> 2, seg = u & 3;
            size_t go = (size_t)(col0 + r) * KP_H + k0 + seg * 8;
            uint32_t so = (uint32_t)(r * 80 + seg * 16);
            cp_async16(base + 2 * S_AT + so,        wh + go, 16);
            cp_async16(base + 2 * S_AT + S_WT + so, wl + go, 16);
        }
    };

    sload(0, 0);
    CP_COMMIT();
    const int NCH = KP_H / 32;   // 10
    for (int ch = 0; ch < NCH; ch++) {
        if (ch + 1 < NCH) {
            sload((ch + 1) & 1, (ch + 1) * 32);
            CP_COMMIT();
            cp_wait<1>();
        } else {
            cp_wait<0>();
        }
        __syncthreads();

        uint32_t base = sb + (ch & 1) * S_STAGE;
        uint32_t sAh = base, sAl = base + S_AT, sWh = base + 2 * S_AT, sWl = base + 2 * S_AT + S_WT;

#pragma unroll
        for (int ks = 0; ks < 2; ks++) {
            const int kstep = ks * 16;
            uint32_t ah[4], al[4], bh[6][2], bl[6][2];
            {
                uint32_t off = (uint32_t)(a_row * 80 + (kstep + a_koff) * 2);
                ldm_x4(ah[0], ah[1], ah[2], ah[3], sAh + off);
                ldm_x4(al[0], al[1], al[2], al[3], sAl + off);
            }
#pragma unroll
            for (int nb = 0; nb < 3; nb++) {
                uint32_t off = (uint32_t)((warp_n + nb * 16 + b_base) * 80 + (kstep + b_koff) * 2);
                ldm_x4(bh[nb*2][0], bh[nb*2][1], bh[nb*2+1][0], bh[nb*2+1][1], sWh + off);
                ldm_x4(bl[nb*2][0], bl[nb*2][1], bl[nb*2+1][0], bl[nb*2+1][1], sWl + off);
            }
#pragma unroll
            for (int nt = 0; nt < 6; nt++) {
                mma_bf16(c[nt][0], c[nt][1], c[nt][2], c[nt][3],
                         ah[0], ah[1], ah[2], ah[3], bh[nt][0], bh[nt][1]);
                mma_bf16(c[nt][0], c[nt][1], c[nt][2], c[nt][3],
                         ah[0], ah[1], ah[2], ah[3], bl[nt][0], bl[nt][1]);
                mma_bf16(c[nt][0], c[nt][1], c[nt][2], c[nt][3],
                         al[0], al[1], al[2], al[3], bh[nt][0], bh[nt][1]);
            }
        }
        __syncthreads();
    }

    // stage gh tile to smem (stride 97 floats)
    float* sC = (float*)smem;
    {
        int r = warp_m + (lane >> 2);
        int cbase = warp_n + (lane & 3) * 2;
#pragma unroll
        for (int nt = 0; nt < 6; nt++) {
            int col = cbase + nt * 8;
            sC[r * 97 + col]           = c[nt][0];
            sC[r * 97 + col + 1]       = c[nt][1];
            sC[(r + 8) * 97 + col]     = c[nt][2];
            sC[(r + 8) * 97 + col + 1] = c[nt][3];
        }
    }
    __syncthreads();

    // gate math: 64 rows x 32 hidden units
    for (int idx = tid; idx < 64 * 32; idx += 256) {
        int r = idx >> 5, hl = idx & 31;
        int h = hbase + hl;
        if (h >= HDIM) continue;
        int mrow = row0 + r;
        bool bwd = mrow >= 512;
        int m = bwd ? mrow - 512 : mrow;
        int aidx = bwd ? (APM - 1 - t) : t;
        int xrow = m * APM + aidx;
        const float* gi  = bwd ? gi_b   : gi_f;
        const float* bih = bwd ? gbih_b : gbih_f;
        const float* bhh = bwd ? gbhh_b : gbhh_f;

        float hr = sC[r * 97 + hl * 3]     + bhh[h];
        float hz = sC[r * 97 + hl * 3 + 1] + bhh[HDIM + h];
        float hn = sC[r * 97 + hl * 3 + 2] + bhh[2 * HDIM + h];
        size_t gio = (size_t)xrow * H3 + 3 * h;
        float ir  = gi[gio]     + bih[h];
        float iz  = gi[gio + 1] + bih[HDIM + h];
        float inn = gi[gio + 2] + bih[2 * HDIM + h];
        float hp = hbuf_cur[(size_t)mrow * HDIM + h];

        float rr = 1.f / (1.f + expf(-(ir + hr)));
        float zz = 1.f / (1.f + expf(-(iz + hz)));
        float nn = tanhf(inn + rr * hn);
        float hnew = (1.f - zz) * nn + zz * hp;

        hbuf_nxt[(size_t)mrow * HDIM + h] = hnew;
        __nv_bfloat16 x, y; bsplit(hnew, x, y);
        hbh_nxt[(size_t)mrow * KP_H + h] = x;
        hbl_nxt[(size_t)mrow * KP_H + h] = y;
        int cc = (bwd ? HDIM : 0) + h;
        o2h[(size_t)xrow * KP_H2 + cc] = x;
        o2l[(size_t)xrow * KP_H2 + cc] = y;
    }
}

// ---------------- conversion / elementwise kernels ----------------
__global__ void conv_split(const float* __restrict__ src, __nv_bfloat16* __restrict__ hi,
                           __nv_bfloat16* __restrict__ lo, int Nn, int Kk, long long NPd, int KPd)
{
    long long total = NPd * (long long)KPd;
    for (long long e = blockIdx.x * (long long)blockDim.x + threadIdx.x; e < total;
         e += (long long)gridDim.x * blockDim.x) {
        int n = (int)(e / KPd), k = (int)(e % KPd);
        float v = (n < Nn && k < Kk) ? src[(size_t)n * Kk + k] : 0.f;
        __nv_bfloat16 h, l; bsplit(v, h, l);
        hi[e] = h; lo[e] = l;
    }
}

// gate-interleaved conversion: dst[j][k], j=3h+g <- src[g*300+h][k'], [960][320]
__global__ void conv_split_int3(const float* __restrict__ src, __nv_bfloat16* __restrict__ hi,
                                __nv_bfloat16* __restrict__ lo)
{
    long long total = (long long)NP_H3 * KP_H;
    for (long long e = blockIdx.x * (long long)blockDim.x + threadIdx.x; e < total;
         e += (long long)gridDim.x * blockDim.x) {
        int j = (int)(e / KP_H), k = (int)(e % KP_H);
        float v = 0.f;
        if (j < H3 && k < HDIM) {
            int g = j % 3, h = j / 3;
            v = src[(size_t)(g * HDIM + h) * HDIM + k];
        }
        __nv_bfloat16 x, y; bsplit(v, x, y);
        hi[e] = x; lo[e] = y;
    }
}

__global__ void agg_update_kernel(const int* __restrict__ a2b, const float* __restrict__ mb,
                                  float* __restrict__ ma)
{
    int i = blockIdx.x;
    __shared__ int idx[MAXNB];
    if (threadIdx.x < MAXNB) idx[threadIdx.x] = a2b[(size_t)i * MAXNB + threadIdx.x];
    __syncthreads();
    int h = threadIdx.x;
    if (h < HDIM) {
        float s = 0.f, m = -INFINITY;
#pragma unroll
        for (int j = 0; j < MAXNB; j++) {
            float v = mb[(size_t)idx[j] * HDIM + h];
            s += v; m = fmaxf(m, v);
        }
        ma[(size_t)i * HDIM + h] += s * m;
    }
}

__global__ void bond_gather_b(const int* __restrict__ b2a, const int* __restrict__ b2revb,
                              const float* __restrict__ ma, const float* __restrict__ mb,
                              __nv_bfloat16* __restrict__ th, __nv_bfloat16* __restrict__ tl)
{
    int e = blockIdx.x;
    __shared__ int sa, sr;
    if (threadIdx.x == 0) { sa = b2a[e]; sr = b2revb[e]; }
    __syncthreads();
    int h = threadIdx.x;
    __nv_bfloat16 z = __float2bfloat16(0.f);
    if (h < HDIM) {
        float v = ma[(size_t)sa * HDIM + h] - mb[(size_t)sr * HDIM + h];
        __nv_bfloat16 x, y; bsplit(v, x, y);
        th[(size_t)e * KP_H + h] = x; tl[(size_t)e * KP_H + h] = y;
    } else if (h < KP_H) {
        th[(size_t)e * KP_H + h] = z; tl[(size_t)e * KP_H + h] = z;
    }
}

__global__ void agg_final_b(const int* __restrict__ a2b, const float* __restrict__ mb,
                            const float* __restrict__ ma, const float* __restrict__ ia,
                            __nv_bfloat16* __restrict__ nh, __nv_bfloat16* __restrict__ nl)
{
    int i = blockIdx.x;
    __shared__ int idx[MAXNB];
    if (threadIdx.x < MAXNB) idx[threadIdx.x] = a2b[(size_t)i * MAXNB + threadIdx.x];
    __syncthreads();
    int h = threadIdx.x;
    size_t base = (size_t)i * KP_H3;
    __nv_bfloat16 z = __float2bfloat16(0.f);
    if (h < HDIM) {
        float s = 0.f, m = -INFINITY;
#pragma unroll
        for (int j = 0; j < MAXNB; j++) {
            float v = mb[(size_t)idx[j] * HDIM + h];
            s += v; m = fmaxf(m, v);
        }
        __nv_bfloat16 x, y;
        bsplit(s * m, x, y);                          nh[base + h] = x;        nl[base + h] = y;
        bsplit(ma[(size_t)i * HDIM + h], x, y);       nh[base + 300 + h] = x;  nl[base + 300 + h] = y;
        bsplit(ia[(size_t)i * HDIM + h], x, y);       nh[base + 600 + h] = x;  nl[base + 600 + h] = y;
    } else if (h < 320) {
        int p = h - 300;
        nh[base + 900 + p] = z; nl[base + 900 + p] = z;
        nh[base + 920 + p] = z; nl[base + 920 + p] = z;
        nh[base + 940 + p] = z; nl[base + 940 + p] = z;
    }
}

// h0 + msgrelu; writes h0 into buffer 0 and zeroes K-pads of BOTH h buffers
__global__ void h0_msg_b(const float* __restrict__ node, float* __restrict__ hbuf0,
                         __nv_bfloat16* __restrict__ hbh, __nv_bfloat16* __restrict__ hbl,
                         __nv_bfloat16* __restrict__ mrh, __nv_bfloat16* __restrict__ mrl)
{
    int m = blockIdx.x;
    int h = threadIdx.x;
    __nv_bfloat16 z = __float2bfloat16(0.f);
    const size_t BUF = (size_t)1024 * KP_H;
    if (h < HDIM) {
        float mx = -INFINITY;
        for (int a = 0; a < APM; a++) {
            float v = node[(size_t)(1 + m * APM + a) * HDIM + h];
            mx = fmaxf(mx, v);
            __nv_bfloat16 x, y; bsplit(fmaxf(v, 0.f), x, y);
            mrh[(size_t)(m * APM + a) * KP_H + h] = x;
            mrl[(size_t)(m * APM + a) * KP_H + h] = y;
        }
        hbuf0[(size_t)m * HDIM + h] = mx;
        hbuf0[(size_t)(512 + m) * HDIM + h] = mx;
        __nv_bfloat16 x, y; bsplit(mx, x, y);
        hbh[(size_t)m * KP_H + h] = x;          hbl[(size_t)m * KP_H + h] = y;
        hbh[(size_t)(512 + m) * KP_H + h] = x;  hbl[(size_t)(512 + m) * KP_H + h] = y;
    } else if (h < KP_H) {
        for (int a = 0; a < APM; a++) {
            mrh[(size_t)(m * APM + a) * KP_H + h] = z;
            mrl[(size_t)(m * APM + a) * KP_H + h] = z;
        }
        // zero pads in both double-buffer halves
        hbh[(size_t)m * KP_H + h] = z;                 hbl[(size_t)m * KP_H + h] = z;
        hbh[(size_t)(512 + m) * KP_H + h] = z;         hbl[(size_t)(512 + m) * KP_H + h] = z;
        hbh[BUF + (size_t)m * KP_H + h] = z;           hbl[BUF + (size_t)m * KP_H + h] = z;
        hbh[BUF + (size_t)(512 + m) * KP_H + h] = z;   hbl[BUF + (size_t)(512 + m) * KP_H + h] = z;
    }
}

__global__ void pad_o2(__nv_bfloat16* __restrict__ oh, __nv_bfloat16* __restrict__ ol)
{
    __nv_bfloat16 z = __float2bfloat16(0.f);
    long long total = (long long)NREAL * 40;
    for (long long e = blockIdx.x * (long long)blockDim.x + threadIdx.x; e < total;
         e += (long long)gridDim.x * blockDim.x) {
        long long r = e / 40; int c = 600 + (int)(e % 40);
        oh[r * KP_H2 + c] = z; ol[r * KP_H2 + c] = z;
    }
}

__global__ void mean_kernel(const float* __restrict__ hid, float* __restrict__ out)
{
    int m = blockIdx.x, h = threadIdx.x;
    if (h >= HDIM) return;
    float s = 0.f;
    for (int a = 0; a < APM; a++) s += hid[(size_t)(m * APM + a) * HDIM + h];
    out[(size_t)m * HDIM + h] = s * (1.f / (float)APM);
}

// ---------------- host ----------------
typedef __nv_bfloat16 bf16;

static inline void tcg(const bf16* Ah, const bf16* Al, int KPd, int wlimit,
                       const bf16* Wh, const bf16* Wl, const bf16* Wh2, const bf16* Wl2, int split,
                       const float* b, const float* b2, const float* add,
                       float* C, float* C2, int rows, int N, int relu)
{
    GArgs a;
    a.Ahi = Ah; a.Alo = Al; a.Whi = Wh; a.Wlo = Wl; a.Whi2 = Wh2; a.Wlo2 = Wl2;
    a.bias = b; a.bias2 = b2; a.addsrc = add; a.C = C; a.C2 = C2;
    a.rows = rows; a.N = N; a.KPd = KPd; a.wlimit = wlimit; a.rowSplit = split; a.doRelu = relu;
    dim3 grid((N + 127) / 128, (rows + 127) / 128);
    mma_gemm<<<grid, GT, GSMEM>>>(a);
}

static inline void conv(const float* s, bf16* h, bf16* l, int Nn, int Kk, long long NPd, int KPd)
{
    long long total = NPd * (long long)KPd;
    int blocks = (int)((total + 255) / 256);
    if (blocks > 8192) blocks = 8192;
    conv_split<<<blocks, 256>>>(s, h, l, Nn, Kk, NPd, KPd);
}

extern "C" void kernel_launch(void* const* d_in, const int* in_sizes, int n_in,
                              void* d_out, int out_size)
{
    (void)out_size;
    const float* f_atoms = (const float*)d_in[0];
    const float* f_bonds = (const float*)d_in[1];
    const int*   a2b     = (const int*)d_in[2];
    const int*   b2a     = (const int*)d_in[3];
    const int*   b2revb  = (const int*)d_in[4];

    int wi = 5;
    for (int j = 5; j < n_in; j++) if (in_sizes[j] == HDIM * AFD) { wi = j; break; }
    const float* W_i_atom = (const float*)d_in[wi + 0];
    const float* W_i_bond = (const float*)d_in[wi + 1];
    const float* W_h      = (const float*)d_in[wi + 2];
    const float* lr_W     = (const float*)d_in[wi + 3];
    const float* W_o_W    = (const float*)d_in[wi + 4];
    const float* W_o_b    = (const float*)d_in[wi + 5];
    const float* gWih_f   = (const float*)d_in[wi + 6];
    const float* gWhh_f   = (const float*)d_in[wi + 7];
    const float* gbih_f   = (const float*)d_in[wi + 8];
    const float* gbhh_f   = (const float*)d_in[wi + 9];
    const float* gWih_b   = (const float*)d_in[wi + 10];
    const float* gWhh_b   = (const float*)d_in[wi + 11];
    const float* gbih_b   = (const float*)d_in[wi + 12];
    const float* gbhh_b   = (const float*)d_in[wi + 13];
    float* out = (float*)d_out;

    cudaFuncSetAttribute(mma_gemm, cudaFuncAttributeMaxDynamicSharedMemorySize, GSMEM);
    cudaFuncSetAttribute(gru_step, cudaFuncAttributeMaxDynamicSharedMemorySize, S_SMEM);

#define SYM(p, s) float* p; cudaGetSymbolAddress((void**)&p, s)
#define SYB(p, s) bf16* p; cudaGetSymbolAddress((void**)&p, s)
    SYM(input_atom, g_input_atom); SYM(input_bond, g_input_bond);
    SYM(msg_atom, g_msg_atom);     SYM(msg_bond, g_msg_bond);
    SYM(node, g_node);             SYM(gi_f, g_gi_f); SYM(gi_b, g_gi_b);
    SYM(hbuf, g_hbuf);             SYM(hid, g_hid);
    SYB(fa_hi, g_fa_hi); SYB(fa_lo, g_fa_lo); SYB(fb_hi, g_fb_hi); SYB(fb_lo, g_fb_lo);
    SYB(tb_hi, g_tb_hi); SYB(tb_lo, g_tb_lo); SYB(nc_hi, g_nc_hi); SYB(nc_lo, g_nc_lo);
    SYB(mr_hi, g_mr_hi); SYB(mr_lo, g_mr_lo); SYB(hb_hi, g_hb_hi); SYB(hb_lo, g_hb_lo);
    SYB(o2_hi, g_o2_hi); SYB(o2_lo, g_o2_lo);
    SYB(wa_hi, g_wa_hi); SYB(wa_lo, g_wa_lo); SYB(wb_hi, g_wb_hi); SYB(wb_lo, g_wb_lo);
    SYB(wh_hi, g_wh_hi); SYB(wh_lo, g_wh_lo); SYB(wlr_hi, g_wlr_hi); SYB(wlr_lo, g_wlr_lo);
    SYB(wo_hi, g_wo_hi); SYB(wo_lo, g_wo_lo);
    SYB(gif_hi, g_gif_hi); SYB(gif_lo, g_gif_lo); SYB(gib_hi, g_gib_hi); SYB(gib_lo, g_gib_lo);
    SYB(ghf_hi, g_ghf_hi); SYB(ghf_lo, g_ghf_lo); SYB(ghb_hi, g_ghb_hi); SYB(ghb_lo, g_ghb_lo);
#undef SYM
#undef SYB

    const int EB = 320;
    const size_t HB  = (size_t)1024 * HDIM;   // hbuf half size
    const size_t HBB = (size_t)1024 * KP_H;   // bf16 half size

    // 0) conversions and pad init
    conv(f_atoms, fa_hi, fa_lo, NATOM, AFD, NATOM, KP_ATOM);
    conv(f_bonds, fb_hi, fb_lo, NBOND, BFD, NBOND, KP_BOND);
    conv(W_i_atom, wa_hi, wa_lo, HDIM, AFD, NP_H, KP_ATOM);
    conv(W_i_bond, wb_hi, wb_lo, HDIM, BFD, NP_H, KP_BOND);
    conv(W_h,                     wh_hi,                     wh_lo,                     HDIM, HDIM, NP_H, KP_H);
    conv(W_h + (size_t)HDIM*HDIM, wh_hi + (size_t)NP_H*KP_H, wh_lo + (size_t)NP_H*KP_H, HDIM, HDIM, NP_H, KP_H);
    conv(lr_W,  wlr_hi, wlr_lo, HDIM, H3, NP_H, KP_H3);
    conv(W_o_W, wo_hi,  wo_lo,  HDIM, H2, NP_H, KP_H2);
    conv_split_int3<<<1200, 256>>>(gWih_f, gif_hi, gif_lo);
    conv_split_int3<<<1200, 256>>>(gWih_b, gib_hi, gib_lo);
    conv_split_int3<<<1200, 256>>>(gWhh_f, ghf_hi, ghf_lo);
    conv_split_int3<<<1200, 256>>>(gWhh_b, ghb_hi, ghb_lo);
    pad_o2<<<4096, 256>>>(o2_hi, o2_lo);

    // 1) input projections
    tcg(fa_hi, fa_lo, KP_ATOM, NP_H, wa_hi, wa_lo, nullptr, nullptr, INT_MAX,
        nullptr, nullptr, nullptr, input_atom, msg_atom, NATOM, HDIM, 1);
    tcg(fb_hi, fb_lo, KP_BOND, NP_H, wb_hi, wb_lo, nullptr, nullptr, INT_MAX,
        nullptr, nullptr, nullptr, input_bond, msg_bond, NBOND, HDIM, 1);

    // 2) message-passing depth loop
    for (int d = 0; d < 2; d++) {
        agg_update_kernel<<<NATOM, EB>>>(a2b, msg_bond, msg_atom);
        bond_gather_b<<<NBOND, EB>>>(b2a, b2revb, msg_atom, msg_bond, tb_hi, tb_lo);
        tcg(tb_hi, tb_lo, KP_H, NP_H,
            wh_hi + (size_t)d * NP_H * KP_H, wh_lo + (size_t)d * NP_H * KP_H,
            nullptr, nullptr, INT_MAX, nullptr, nullptr, input_bond,
            msg_bond, nullptr, NBOND, HDIM, 1);
    }

    // 3) final agg + concat + lr GEMM
    agg_final_b<<<NATOM, EB>>>(a2b, msg_bond, msg_atom, input_atom, nc_hi, nc_lo);
    tcg(nc_hi, nc_lo, KP_H3, NP_H, wlr_hi, wlr_lo, nullptr, nullptr, INT_MAX,
        nullptr, nullptr, nullptr, node, nullptr, NATOM, HDIM, 0);

    // 4) h0 + msgrelu (init h double-buffers)
    h0_msg_b<<<MOLS, EB>>>(node, hbuf, hb_hi, hb_lo, mr_hi, mr_lo);

    // 5) GRU input gates (gate-interleaved output; biases added in gru_step)
    tcg(mr_hi, mr_lo, KP_H, NP_H3, gif_hi, gif_lo, nullptr, nullptr, INT_MAX,
        nullptr, nullptr, nullptr, gi_f, nullptr, NREAL, H3, 0);
    tcg(mr_hi, mr_lo, KP_H, NP_H3, gib_hi, gib_lo, nullptr, nullptr, INT_MAX,
        nullptr, nullptr, nullptr, gi_b, nullptr, NREAL, H3, 0);

    // 6) GRU recurrence: ONE fused launch per step, 160 blocks each
    for (int t = 0; t < APM; t++) {
        int cur = t & 1, nxt = cur ^ 1;
        gru_step<<<dim3(10, 16), 256, S_SMEM>>>(
            hb_hi + cur * HBB, hb_lo + cur * HBB,
            ghf_hi, ghf_lo, ghb_hi, ghb_lo,
            gi_f, gi_b, gbih_f, gbhh_f, gbih_b, gbhh_b,
            hbuf + cur * HB, hbuf + nxt * HB,
            hb_hi + nxt * HBB, hb_lo + nxt * HBB,
            o2_hi, o2_lo, t);
    }

    // 7) output projection + mean
    tcg(o2_hi, o2_lo, KP_H2, NP_H, wo_hi, wo_lo, nullptr, nullptr, INT_MAX,
        W_o_b, nullptr, nullptr, hid, nullptr, NREAL, HDIM, 1);
    mean_kernel<<<MOLS, EB>>>(hid, out);
}